// round 16
// baseline (speedup 1.0000x reference)
#include <cuda_runtime.h>
#include <cuda_bf16.h>
#include <math_constants.h>
#include <cstdint>

// Fused ConvTranspose3d(3->16,k3,s2,p1,op1)+bias+MaxPool3d(2)+softmax-sub+swish+chmax
// via Ampere-style mma.sync bf16 (base compute_103 -- tcgen05 unavailable in harness PTX).
// Per warp-row GEMM: D[64 vox][128 = ch*8+cand] = A[64][K32] . B[128][K32]^T,
// split-bf16 (xh+xl, wh+wl; 3 passes: Ah.Bh + Ah.Bl + Al.Bh), fp32 TC accum.
// n8-tile = one channel's 8 pool candidates -> maxpool = 1 reg-max + 2 quad shuffles.

#define DIM 64
#define CIN 3
#define COUT 16
#define XSTR 66
#define BSTR 136   // B row stride (elems): 272B = 16B-aligned rows, conflict-free ldmatrix

// W_eff[n=ch*8+cand][k=cin*8+dd*4+hh*2+ww]; invalid taps 0.
static __device__ __forceinline__ float weff(const float* __restrict__ wgt, int ch, int cand, int k) {
    const int cin = k >> 3, dd = (k >> 2) & 1, hh = (k >> 1) & 1, ww = k & 1;
    const int pd = (cand >> 2) & 1, ph = (cand >> 1) & 1, pw = cand & 1;
    const int kd = pd ? (dd ? 0 : 2) : (dd ? -1 : 1);
    const int kh = ph ? (hh ? 0 : 2) : (hh ? -1 : 1);
    const int kw = pw ? (ww ? 0 : 2) : (ww ? -1 : 1);
    if (kd < 0 || kh < 0 || kw < 0) return 0.f;
    return __ldg(&wgt[(cin * COUT + ch) * 27 + kd * 9 + kh * 3 + kw]);
}

static __device__ __forceinline__ uint32_t smaddr(const void* p) {
    uint32_t a;
    asm("{ .reg .u64 t; cvta.to.shared.u64 t, %1; cvt.u32.u64 %0, t; }" : "=r"(a) : "l"(p));
    return a;
}
static __device__ __forceinline__ uint32_t pk2h(float a, float b) {
    __nv_bfloat162 t = __floats2bfloat162_rn(a, b);   // a -> low half
    return *reinterpret_cast<uint32_t*>(&t);
}
static __device__ __forceinline__ float bfh(float x) {
    return __bfloat162float(__float2bfloat16(x));
}
static __device__ __forceinline__ uint32_t pk2l(float a, float b) {
    return pk2h(a - bfh(a), b - bfh(b));
}
static __device__ __forceinline__ void ldmB(uint32_t& b0, uint32_t& b1, uint32_t addr) {
    asm volatile("ldmatrix.sync.aligned.m8n8.x2.trans.shared.b16 {%0,%1}, [%2];"
                 : "=r"(b0), "=r"(b1) : "r"(addr));
}
static __device__ __forceinline__ void mma16816(float* d, const uint32_t* a, uint32_t b0, uint32_t b1) {
    asm volatile(
        "mma.sync.aligned.m16n8k16.row.col.f32.bf16.bf16.f32 "
        "{%0,%1,%2,%3}, {%4,%5,%6,%7}, {%8,%9}, {%0,%1,%2,%3};"
        : "+f"(d[0]), "+f"(d[1]), "+f"(d[2]), "+f"(d[3])
        : "r"(a[0]), "r"(a[1]), "r"(a[2]), "r"(a[3]), "r"(b0), "r"(b1));
}

__global__ __launch_bounds__(128) void fused_mma_kernel(
    const float* __restrict__ x, const float* __restrict__ wgt,
    const float* __restrict__ bias_g, const float* __restrict__ sub_g,
    float* __restrict__ out)
{
    __shared__ float xt[4][12][XSTR];                 // per-warp x tile
    __shared__ __nv_bfloat16 Bh[32 * BSTR];           // W_eff hi, [k][n] rows
    __shared__ __nv_bfloat16 Bl[32 * BSTR];           // W_eff lo
    __shared__ float e_sm[4][17][64];                 // [ch 0..15][vox] + row16 = S
    __shared__ float bias_sm[COUT], sub_sm[COUT];

    const int tid  = threadIdx.x;
    const int lane = tid & 31;
    const int wid  = tid >> 5;
    const int g    = lane >> 2;    // mma row group
    const int tg   = lane & 3;     // mma thread-in-quad

    // ---- one-time: build B (split bf16), bias/sub ----
    for (int idx = tid; idx < 32 * 128; idx += 128) {
        const int k = idx >> 7, n = idx & 127;
        const float v = (k < 24) ? weff(wgt, n >> 3, n & 7, k) : 0.f;
        const float h = bfh(v);
        Bh[k * BSTR + n] = __float2bfloat16(h);
        Bl[k * BSTR + n] = __float2bfloat16(v - h);
    }
    if (tid < COUT) {
        bias_sm[tid] = __ldg(&bias_g[tid]);
        sub_sm[tid]  = __ldg(&sub_g[tid]);
    }
    __syncthreads();

    const uint32_t bh_base = smaddr(Bh), bl_base = smaddr(Bl);

    const int gwarp  = blockIdx.x * 4 + wid;
    const int nwarps = gridDim.x * 4;
    const int nrows  = 4 * DIM * DIM;

    for (int row = gwarp; row < nrows; row += nwarps) {
        const int h = row & 63, d = (row >> 6) & 63, n = row >> 12;

        // ---- stage x tile (12 combs x 66, zero-padded) ----
        #pragma unroll
        for (int comb = 0; comb < 12; ++comb) {
            const int cin = comb >> 2, dd = (comb >> 1) & 1, hh = comb & 1;
            const int dc = d + dd, hc = h + hh;
            const bool ok = (dc < DIM) && (hc < DIM);
            const float* src = x + (((n * CIN + cin) * DIM + dc) * DIM + hc) * DIM;
            #pragma unroll
            for (int wp = lane; wp < XSTR; wp += 32) {
                float v = 0.f;
                if (ok && wp < DIM) v = __ldg(&src[wp]);
                xt[wid][comb][wp] = v;
            }
        }
        __syncwarp();

        #pragma unroll 1
        for (int mt = 0; mt < 4; ++mt) {
            const int vb = mt * 16;

            // ---- A fragments built directly in registers ----
            // k-pair {2t,2t+1} <-> comb = t, ww = 0/1 ; combs needed: tg, tg+4, tg+8
            float xv[3][4];
            #pragma unroll
            for (int cs = 0; cs < 3; ++cs) {
                const float* xr = xt[wid][tg + cs * 4];
                xv[cs][0] = xr[vb + g];
                xv[cs][1] = xr[vb + g + 1];
                xv[cs][2] = xr[vb + g + 8];
                xv[cs][3] = xr[vb + g + 9];
            }
            uint32_t ah[2][4], al[2][4];
            ah[0][0] = pk2h(xv[0][0], xv[0][1]); ah[0][1] = pk2h(xv[0][2], xv[0][3]);
            ah[0][2] = pk2h(xv[1][0], xv[1][1]); ah[0][3] = pk2h(xv[1][2], xv[1][3]);
            ah[1][0] = pk2h(xv[2][0], xv[2][1]); ah[1][1] = pk2h(xv[2][2], xv[2][3]);
            ah[1][2] = 0u;                        ah[1][3] = 0u;   // k 24..31 pad
            al[0][0] = pk2l(xv[0][0], xv[0][1]); al[0][1] = pk2l(xv[0][2], xv[0][3]);
            al[0][2] = pk2l(xv[1][0], xv[1][1]); al[0][3] = pk2l(xv[1][2], xv[1][3]);
            al[1][0] = pk2l(xv[2][0], xv[2][1]); al[1][1] = pk2l(xv[2][2], xv[2][3]);
            al[1][2] = 0u;                        al[1][3] = 0u;

            float S0 = 0.f, S1 = 0.f;

            #pragma unroll
            for (int nh = 0; nh < 2; ++nh) {
                float dacc[8][4];
                #pragma unroll
                for (int i = 0; i < 8; ++i)
                    #pragma unroll
                    for (int j = 0; j < 4; ++j) dacc[i][j] = 0.f;

                // 3 passes: Ah.Bh, Ah.Bl, Al.Bh
                #pragma unroll
                for (int pass = 0; pass < 3; ++pass) {
                    const uint32_t bbase = (pass == 1) ? bl_base : bh_base;
                    const uint32_t (*aa)[4] = (pass == 2) ? al : ah;
                    #pragma unroll
                    for (int nt = 0; nt < 8; ++nt) {
                        const uint32_t coff = ((nh * 8 + nt) * 8) * 2;
                        uint32_t b0, b1;
                        ldmB(b0, b1, bbase + ((lane & 15) * BSTR) * 2 + coff);
                        mma16816(dacc[nt], aa[0], b0, b1);
                        ldmB(b0, b1, bbase + ((16 + (lane & 15)) * BSTR) * 2 + coff);
                        mma16816(dacc[nt], aa[1], b0, b1);
                    }
                }

                // ---- epilogue pass1: maxpool(8 cands) + bias + exp ----
                #pragma unroll
                for (int nt = 0; nt < 8; ++nt) {
                    const int ch = nh * 8 + nt;
                    float m0 = fmaxf(dacc[nt][0], dacc[nt][1]);   // vox vb+g
                    float m1 = fmaxf(dacc[nt][2], dacc[nt][3]);   // vox vb+g+8
                    m0 = fmaxf(m0, __shfl_xor_sync(0xffffffffu, m0, 1));
                    m1 = fmaxf(m1, __shfl_xor_sync(0xffffffffu, m1, 1));
                    m0 = fmaxf(m0, __shfl_xor_sync(0xffffffffu, m0, 2));
                    m1 = fmaxf(m1, __shfl_xor_sync(0xffffffffu, m1, 2));
                    const float e0 = __expf(m0 + bias_sm[ch]);
                    const float e1 = __expf(m1 + bias_sm[ch]);
                    S0 += e0; S1 += e1;
                    if (tg == 0) {
                        e_sm[wid][ch][vb + g]     = e0;
                        e_sm[wid][ch][vb + 8 + g] = e1;
                    }
                }
            }
            if (tg == 0) {
                e_sm[wid][16][vb + g]     = S0;
                e_sm[wid][16][vb + 8 + g] = S1;
            }
        }
        __syncwarp();

        // ---- pass2: softmax -> subtract -> swish -> channel max ----
        float* orow = out + row * DIM;
        #pragma unroll
        for (int rep = 0; rep < 2; ++rep) {
            const int v = lane + rep * 32;
            float rS;
            asm("rcp.approx.f32 %0, %1;" : "=f"(rS) : "f"(e_sm[wid][16][v]));
            float best = -CUDART_INF_F;
            #pragma unroll
            for (int ch = 0; ch < COUT; ++ch) {
                const float z = fmaf(e_sm[wid][ch][v], rS, -sub_sm[ch]);
                best = fmaxf(best, __fdividef(z, 1.f + __expf(-z)));
            }
            orow[v] = best;
        }
        __syncwarp();   // before next row overwrites xt / e_sm
    }
}

extern "C" void kernel_launch(void* const* d_in, const int* in_sizes, int n_in,
                              void* d_out, int out_size) {
    const float* x   = (const float*)d_in[0];
    const float* w   = (const float*)d_in[1];
    const float* b   = (const float*)d_in[2];
    const float* sub = (const float*)d_in[3];
    float* out = (float*)d_out;
    (void)in_sizes; (void)n_in; (void)out_size;

    int dev = 0, sms = 148, bpm = 2;
    cudaGetDevice(&dev);
    cudaDeviceGetAttribute(&sms, cudaDevAttrMultiProcessorCount, dev);
    cudaOccupancyMaxActiveBlocksPerMultiprocessor(&bpm, fused_mma_kernel, 128, 0);
    if (bpm < 1) bpm = 1;
    fused_mma_kernel<<<sms * bpm, 128>>>(x, w, b, sub, out);
}